// round 1
// baseline (speedup 1.0000x reference)
#include <cuda_runtime.h>
#include <math.h>
#include <stdint.h>

// Problem dims
constexpr int CB  = 4;
constexpr int CS  = 1024;
constexpr int CD  = 1024;
constexpr int CH  = 16;
constexpr int CDK = 64;
constexpr int BH   = CB * CH;   // 64
constexpr int ROWS = CB * CS;   // 4096
constexpr float LN_EPS = 1e-5f;

// Scratch (device globals: no cudaMalloc allowed)
__device__ float g_valid[ROWS];
__device__ float g_Q[(size_t)BH * CS * CDK];
__device__ float g_K[(size_t)BH * CS * CDK];
__device__ float g_V[(size_t)BH * CS * CDK];
__device__ float g_E[(size_t)BH * CS * CS];   // 256 MB attention scratch
__device__ float g_Z[(size_t)ROWS * CD];
__device__ float g_Hb[(size_t)ROWS * CD];
__device__ float g_F[(size_t)ROWS * CD];
__device__ float g_G[(size_t)ROWS * CD];

// ---------------- reductions ----------------
__device__ __forceinline__ float warpMax(float v) {
    #pragma unroll
    for (int o = 16; o; o >>= 1) v = fmaxf(v, __shfl_xor_sync(0xffffffffu, v, o));
    return v;
}
__device__ __forceinline__ float warpSum(float v) {
    #pragma unroll
    for (int o = 16; o; o >>= 1) v += __shfl_xor_sync(0xffffffffu, v, o);
    return v;
}

// ---------------- valid-row flags ----------------
__global__ void k_valid(const float* __restrict__ x, float* __restrict__ valid) {
    int row = blockIdx.x;
    const float* xr = x + (size_t)row * CD;
    int any = 0;
    for (int i = threadIdx.x; i < CD; i += blockDim.x) any |= (xr[i] != 0.0f);
    any = __syncthreads_or(any);
    if (threadIdx.x == 0) valid[row] = any ? 1.0f : 0.0f;
}

// ---------------- tiled GEMM building blocks ----------------
// 64x64 output tile, BK=16, 256 threads, each thread 4x4.
// sA[c][r]: transposed store (depth-major), padded row 68 for conflict-free float4 reads.

__device__ __forceinline__ void load_At(float (*s)[68], const float* __restrict__ base, int ld) {
    int t = threadIdx.x;
    #pragma unroll
    for (int i = 0; i < 4; i++) {
        int idx = t + i * 256;
        int r = idx >> 4, c = idx & 15;
        s[c][r] = base[(size_t)r * ld + c];
    }
}
__device__ __forceinline__ void load_Bn(float (*s)[68], const float* __restrict__ base, int ld) {
    int t = threadIdx.x;
    #pragma unroll
    for (int i = 0; i < 4; i++) {
        int idx = t + i * 256;
        int k = idx >> 6, e = idx & 63;
        s[k][e] = base[(size_t)k * ld + e];
    }
}
__device__ __forceinline__ void mm16(float acc[4][4], const float (*sA)[68], const float (*sB)[68],
                                     int ry, int cx) {
    #pragma unroll
    for (int kk = 0; kk < 16; kk++) {
        float4 a = *(const float4*)&sA[kk][ry];
        float4 b = *(const float4*)&sB[kk][cx];
        float av[4] = {a.x, a.y, a.z, a.w};
        float bv[4] = {b.x, b.y, b.z, b.w};
        #pragma unroll
        for (int i = 0; i < 4; i++)
            #pragma unroll
            for (int j = 0; j < 4; j++)
                acc[i][j] += av[i] * bv[j];
    }
}

// ---------------- QKV projection ----------------
// grid: (S/64, 3, B*H). out[b,h,s,e] = sum_d x[b,s,d] * W[h,d,e]
__global__ void k_qkv(const float* __restrict__ x,
                      const float* __restrict__ Wq, const float* __restrict__ Wk,
                      const float* __restrict__ Wv,
                      float* __restrict__ pQ, float* __restrict__ pK, float* __restrict__ pV) {
    __shared__ float sA[16][68];
    __shared__ float sB[16][68];
    int bh = blockIdx.z, b = bh >> 4, h = bh & 15;
    int which = blockIdx.y;
    const float* W = (which == 0 ? Wq : which == 1 ? Wk : Wv) + (size_t)h * CD * CDK;
    float* out = (which == 0 ? pQ : which == 1 ? pK : pV)
                 + (size_t)bh * CS * CDK + (size_t)blockIdx.x * 64 * CDK;
    const float* Xb = x + (size_t)b * CS * CD + (size_t)blockIdx.x * 64 * CD;

    float acc[4][4] = {};
    int ry = (threadIdx.x >> 4) << 2, cx = (threadIdx.x & 15) << 2;
    for (int k0 = 0; k0 < CD; k0 += 16) {
        load_At(sA, Xb + k0, CD);
        load_Bn(sB, W + (size_t)k0 * CDK, CDK);
        __syncthreads();
        mm16(acc, sA, sB, ry, cx);
        __syncthreads();
    }
    #pragma unroll
    for (int i = 0; i < 4; i++) {
        float4 v = {acc[i][0], acc[i][1], acc[i][2], acc[i][3]};
        *(float4*)&out[(size_t)(ry + i) * CDK + cx] = v;
    }
}

// ---------------- energy = (Q K^T) * scale, column-masked ----------------
// grid: (S/64 ktiles, S/64 qtiles, B*H)
__global__ void k_energy(const float* __restrict__ pQ, const float* __restrict__ pK,
                         const float* __restrict__ valid, float* __restrict__ pE) {
    __shared__ float sA[16][68];
    __shared__ float sB[16][68];
    int bh = blockIdx.z, b = bh >> 4;
    const float* Qb = pQ + (size_t)bh * CS * CDK + (size_t)blockIdx.y * 64 * CDK;
    const float* Kb = pK + (size_t)bh * CS * CDK + (size_t)blockIdx.x * 64 * CDK;
    float* Eo = pE + (size_t)bh * CS * CS + (size_t)blockIdx.y * 64 * CS + (size_t)blockIdx.x * 64;

    float acc[4][4] = {};
    int ry = (threadIdx.x >> 4) << 2, cx = (threadIdx.x & 15) << 2;
    for (int k0 = 0; k0 < CDK; k0 += 16) {
        load_At(sA, Qb + k0, CDK);
        load_At(sB, Kb + k0, CDK);   // transposed: sB[depth][out-col]
        __syncthreads();
        mm16(acc, sA, sB, ry, cx);
        __syncthreads();
    }
    int kbase = blockIdx.x * 64 + cx;
    float cm[4];
    #pragma unroll
    for (int j = 0; j < 4; j++) cm[j] = valid[b * CS + kbase + j];
    #pragma unroll
    for (int i = 0; i < 4; i++) {
        #pragma unroll
        for (int j = 0; j < 4; j++) {
            float val = (cm[j] != 0.0f) ? acc[i][j] * 0.125f : -1e30f;
            Eo[(size_t)(ry + i) * CS + cx + j] = val;
        }
    }
}

// ---------------- row softmax (in place), 1024 cols ----------------
__global__ void k_softmax(float* __restrict__ E) {
    float* row = E + (size_t)blockIdx.x * CS;
    int t = threadIdx.x;
    float4 v = ((float4*)row)[t];
    float m = fmaxf(fmaxf(v.x, v.y), fmaxf(v.z, v.w));
    __shared__ float sm[8];
    __shared__ float ss[8];
    m = warpMax(m);
    if ((t & 31) == 0) sm[t >> 5] = m;
    __syncthreads();
    float mm = sm[0];
    #pragma unroll
    for (int i = 1; i < 8; i++) mm = fmaxf(mm, sm[i]);
    float e0 = __expf(v.x - mm), e1 = __expf(v.y - mm);
    float e2 = __expf(v.z - mm), e3 = __expf(v.w - mm);
    float s = e0 + e1 + e2 + e3;
    s = warpSum(s);
    if ((t & 31) == 0) ss[t >> 5] = s;
    __syncthreads();
    float tot = 0.f;
    #pragma unroll
    for (int i = 0; i < 8; i++) tot += ss[i];
    float inv = 1.0f / tot;
    v.x = e0 * inv; v.y = e1 * inv; v.z = e2 * inv; v.w = e3 * inv;
    ((float4*)row)[t] = v;
}

// ---------------- attn = P @ V, row-masked, written as [B,S,D] ----------------
// grid: (S/64 qtiles, B*H)
__global__ void k_pv(const float* __restrict__ pE, const float* __restrict__ pV,
                     const float* __restrict__ valid, float* __restrict__ pZ) {
    __shared__ float sA[16][68];
    __shared__ float sB[16][68];
    int bh = blockIdx.y, b = bh >> 4, h = bh & 15;
    int q0 = blockIdx.x * 64;
    const float* P  = pE + (size_t)bh * CS * CS + (size_t)q0 * CS;
    const float* Vb = pV + (size_t)bh * CS * CDK;

    float acc[4][4] = {};
    int ry = (threadIdx.x >> 4) << 2, cx = (threadIdx.x & 15) << 2;
    for (int k0 = 0; k0 < CS; k0 += 16) {
        load_At(sA, P + k0, CS);
        load_Bn(sB, Vb + (size_t)k0 * CDK, CDK);
        __syncthreads();
        mm16(acc, sA, sB, ry, cx);
        __syncthreads();
    }
    #pragma unroll
    for (int i = 0; i < 4; i++) {
        float vf = valid[b * CS + q0 + ry + i];
        float4 o = {acc[i][0] * vf, acc[i][1] * vf, acc[i][2] * vf, acc[i][3] * vf};
        *(float4*)&pZ[(size_t)(b * CS + q0 + ry + i) * CD + h * 64 + cx] = o;
    }
}

// ---------------- residual add + LayerNorm ----------------
__global__ void k_addln(const float* __restrict__ A, const float* __restrict__ Bv,
                        const float* __restrict__ g, const float* __restrict__ bb,
                        float* __restrict__ out) {
    int row = blockIdx.x, t = threadIdx.x;
    float4 a = ((const float4*)(A  + (size_t)row * CD))[t];
    float4 b = ((const float4*)(Bv + (size_t)row * CD))[t];
    float4 v = {a.x + b.x, a.y + b.y, a.z + b.z, a.w + b.w};
    float s = v.x + v.y + v.z + v.w;
    float q = v.x * v.x + v.y * v.y + v.z * v.z + v.w * v.w;
    __shared__ float sr1[8];
    __shared__ float sr2[8];
    s = warpSum(s); q = warpSum(q);
    if ((t & 31) == 0) { sr1[t >> 5] = s; sr2[t >> 5] = q; }
    __syncthreads();
    float S = 0.f, Q = 0.f;
    #pragma unroll
    for (int i = 0; i < 8; i++) { S += sr1[i]; Q += sr2[i]; }
    float mu = S * (1.0f / CD);
    float var = Q * (1.0f / CD) - mu * mu;
    float rs = rsqrtf(var + LN_EPS);
    float4 gg = ((const float4*)g)[t];
    float4 bv2 = ((const float4*)bb)[t];
    float4 o;
    o.x = (v.x - mu) * rs * gg.x + bv2.x;
    o.y = (v.y - mu) * rs * gg.y + bv2.y;
    o.z = (v.z - mu) * rs * gg.z + bv2.z;
    o.w = (v.w - mu) * rs * gg.w + bv2.w;
    ((float4*)(out + (size_t)row * CD))[t] = o;
}

// ---------------- FC (NT GEMM): out[r,j] = act(sum_d A[r,d]*W[j,d] + bias[j]) * valid[r]
// grid: (D/64 jtiles, ROWS/64 rtiles)
template <bool RELU>
__global__ void k_fc(const float* __restrict__ A, const float* __restrict__ W,
                     const float* __restrict__ bias, const float* __restrict__ valid,
                     float* __restrict__ out) {
    __shared__ float sA[16][68];
    __shared__ float sB[16][68];
    int r0 = blockIdx.y * 64, j0 = blockIdx.x * 64;
    const float* Ab = A + (size_t)r0 * CD;
    const float* Wb = W + (size_t)j0 * CD;

    float acc[4][4] = {};
    int ry = (threadIdx.x >> 4) << 2, cx = (threadIdx.x & 15) << 2;
    for (int k0 = 0; k0 < CD; k0 += 16) {
        load_At(sA, Ab + k0, CD);
        load_At(sB, Wb + k0, CD);   // W rows are output cols
        __syncthreads();
        mm16(acc, sA, sB, ry, cx);
        __syncthreads();
    }
    float bj[4];
    #pragma unroll
    for (int j = 0; j < 4; j++) bj[j] = bias[j0 + cx + j];
    #pragma unroll
    for (int i = 0; i < 4; i++) {
        float vf = valid[r0 + ry + i];
        float4 o;
        float t0 = acc[i][0] + bj[0], t1 = acc[i][1] + bj[1];
        float t2 = acc[i][2] + bj[2], t3 = acc[i][3] + bj[3];
        if (RELU) { t0 = fmaxf(t0, 0.f); t1 = fmaxf(t1, 0.f); t2 = fmaxf(t2, 0.f); t3 = fmaxf(t3, 0.f); }
        o.x = t0 * vf; o.y = t1 * vf; o.z = t2 * vf; o.w = t3 * vf;
        *(float4*)&out[(size_t)(r0 + ry + i) * CD + j0 + cx] = o;
    }
}

// ---------------- launch ----------------
extern "C" void kernel_launch(void* const* d_in, const int* in_sizes, int n_in,
                              void* d_out, int out_size) {
    const float* x     = (const float*)d_in[0];
    const float* Wq    = (const float*)d_in[1];
    const float* Wk    = (const float*)d_in[2];
    const float* Wv    = (const float*)d_in[3];
    const float* ln1_g = (const float*)d_in[4];
    const float* ln1_b = (const float*)d_in[5];
    const float* fc1_w = (const float*)d_in[6];
    const float* fc1_b = (const float*)d_in[7];
    const float* fc2_w = (const float*)d_in[8];
    const float* fc2_b = (const float*)d_in[9];
    const float* ln2_g = (const float*)d_in[10];
    const float* ln2_b = (const float*)d_in[11];
    float* out = (float*)d_out;

    static float *pValid = nullptr, *pQ, *pK, *pV, *pE, *pZ, *pH, *pF, *pG;
    if (!pValid) {
        cudaGetSymbolAddress((void**)&pValid, g_valid);
        cudaGetSymbolAddress((void**)&pQ, g_Q);
        cudaGetSymbolAddress((void**)&pK, g_K);
        cudaGetSymbolAddress((void**)&pV, g_V);
        cudaGetSymbolAddress((void**)&pE, g_E);
        cudaGetSymbolAddress((void**)&pZ, g_Z);
        cudaGetSymbolAddress((void**)&pH, g_Hb);
        cudaGetSymbolAddress((void**)&pF, g_F);
        cudaGetSymbolAddress((void**)&pG, g_G);
    }

    k_valid<<<ROWS, 256>>>(x, pValid);
    k_qkv<<<dim3(CS / 64, 3, BH), 256>>>(x, Wq, Wk, Wv, pQ, pK, pV);
    k_energy<<<dim3(CS / 64, CS / 64, BH), 256>>>(pQ, pK, pValid, pE);
    k_softmax<<<BH * CS, 256>>>(pE);
    k_pv<<<dim3(CS / 64, BH), 256>>>(pE, pV, pValid, pZ);
    k_addln<<<ROWS, 256>>>(x, pZ, ln1_g, ln1_b, pH);
    k_fc<true><<<dim3(CD / 64, ROWS / 64), 256>>>(pH, fc1_w, fc1_b, pValid, pF);
    k_fc<false><<<dim3(CD / 64, ROWS / 64), 256>>>(pF, fc2_w, fc2_b, pValid, pG);
    k_addln<<<ROWS, 256>>>(pH, pG, ln2_g, ln2_b, out);
}

// round 3
// speedup vs baseline: 2.6619x; 2.6619x over previous
#include <cuda_runtime.h>
#include <math.h>
#include <stdint.h>

// Problem dims
constexpr int CB  = 4;
constexpr int CS  = 1024;
constexpr int CD  = 1024;
constexpr int CH  = 16;
constexpr int CDK = 64;
constexpr int BH   = CB * CH;   // 64
constexpr int ROWS = CB * CS;   // 4096
constexpr float LN_EPS = 1e-5f;

// Scratch (device globals: no cudaMalloc allowed)
__device__ float g_valid[ROWS];
__device__ float g_Q[(size_t)BH * CS * CDK];
__device__ float g_K[(size_t)BH * CS * CDK];
__device__ float g_V[(size_t)BH * CS * CDK];
__device__ float g_E[(size_t)BH * CS * CS];   // 256 MB attention scratch
__device__ float g_Z[(size_t)ROWS * CD];
__device__ float g_Hb[(size_t)ROWS * CD];
__device__ float g_F[(size_t)ROWS * CD];
__device__ float g_G[(size_t)ROWS * CD];

// ---------------- helpers ----------------
__device__ __forceinline__ float warpMax(float v) {
    #pragma unroll
    for (int o = 16; o; o >>= 1) v = fmaxf(v, __shfl_xor_sync(0xffffffffu, v, o));
    return v;
}
__device__ __forceinline__ float warpSum(float v) {
    #pragma unroll
    for (int o = 16; o; o >>= 1) v += __shfl_xor_sync(0xffffffffu, v, o);
    return v;
}
__device__ __forceinline__ uint32_t f2tf(float f) {
    uint32_t u;
    asm("cvt.rna.tf32.f32 %0, %1;" : "=r"(u) : "f"(f));
    return u;
}
__device__ __forceinline__ void mma8(float c[4], const uint32_t a[4], const uint32_t b[2]) {
    asm volatile(
        "mma.sync.aligned.m16n8k8.row.col.f32.tf32.tf32.f32 "
        "{%0,%1,%2,%3},{%4,%5,%6,%7},{%8,%9},{%0,%1,%2,%3};"
        : "+f"(c[0]), "+f"(c[1]), "+f"(c[2]), "+f"(c[3])
        : "r"(a[0]), "r"(a[1]), "r"(a[2]), "r"(a[3]), "r"(b[0]), "r"(b[1]));
}

// ---------------- tf32 MMA GEMM core ----------------
// Block tile 128(M) x 64(N), BK=32, 256 threads = 8 warps in 4x2 grid,
// each warp owns a 32x32 sub-tile = 2(m) x 4(n) m16n8k8 fragments.
// NN: B stored [K,N] row-major. NT: B stored [N,K] row-major.
template<bool NN>
__device__ __forceinline__ void gemm_core(const float* __restrict__ A, size_t lda,
                                          const float* __restrict__ B, size_t ldb,
                                          int K, float acc[2][4][4]) {
    __shared__ uint32_t sA[128][36];   // [m][k], pad -> frag loads conflict-free
    __shared__ uint32_t sB[2304];      // NT: [n][36]; NN: [k][72]
    const int t = threadIdx.x, lane = t & 31, w = t >> 5;
    const int wr = w >> 1, wc = w & 1;

    for (int k0 = 0; k0 < K; k0 += 32) {
        // ---- A tile 128x32 ----
        #pragma unroll
        for (int i = 0; i < 4; i++) {
            int row = (t >> 3) + (i << 5);
            int c4  = (t & 7) << 2;
            float4 v = *(const float4*)(A + (size_t)row * lda + k0 + c4);
            uint4 u = { f2tf(v.x), f2tf(v.y), f2tf(v.z), f2tf(v.w) };
            *(uint4*)&sA[row][c4] = u;
        }
        // ---- B tile ----
        if (NN) {
            #pragma unroll
            for (int i = 0; i < 2; i++) {
                int k  = (t >> 4) + (i << 4);
                int n4 = (t & 15) << 2;
                float4 v = *(const float4*)(B + (size_t)(k0 + k) * ldb + n4);
                uint4 u = { f2tf(v.x), f2tf(v.y), f2tf(v.z), f2tf(v.w) };
                *(uint4*)&sB[k * 72 + n4] = u;
            }
        } else {
            #pragma unroll
            for (int i = 0; i < 2; i++) {
                int n  = (t >> 3) + (i << 5);
                int c4 = (t & 7) << 2;
                float4 v = *(const float4*)(B + (size_t)n * ldb + k0 + c4);
                uint4 u = { f2tf(v.x), f2tf(v.y), f2tf(v.z), f2tf(v.w) };
                *(uint4*)&sB[n * 36 + c4] = u;
            }
        }
        __syncthreads();

        #pragma unroll
        for (int ks = 0; ks < 32; ks += 8) {
            uint32_t af[2][4], bf[4][2];
            #pragma unroll
            for (int ms = 0; ms < 2; ms++) {
                int r0 = wr * 32 + ms * 16 + (lane >> 2);
                int kc = ks + (lane & 3);
                af[ms][0] = sA[r0][kc];
                af[ms][1] = sA[r0 + 8][kc];
                af[ms][2] = sA[r0][kc + 4];
                af[ms][3] = sA[r0 + 8][kc + 4];
            }
            #pragma unroll
            for (int ns = 0; ns < 4; ns++) {
                int n0 = wc * 32 + ns * 8 + (lane >> 2);
                int kc = ks + (lane & 3);
                if (NN) {
                    bf[ns][0] = sB[kc * 72 + n0];
                    bf[ns][1] = sB[(kc + 4) * 72 + n0];
                } else {
                    bf[ns][0] = sB[n0 * 36 + kc];
                    bf[ns][1] = sB[n0 * 36 + kc + 4];
                }
            }
            #pragma unroll
            for (int ms = 0; ms < 2; ms++)
                #pragma unroll
                for (int ns = 0; ns < 4; ns++)
                    mma8(acc[ms][ns], af[ms], bf[ns]);
        }
        __syncthreads();
    }
}

// ---------------- valid-row flags ----------------
__global__ void k_valid(const float* __restrict__ x, float* __restrict__ valid) {
    int row = blockIdx.x;
    const float* xr = x + (size_t)row * CD;
    int any = 0;
    for (int i = threadIdx.x; i < CD; i += blockDim.x) any |= (xr[i] != 0.0f);
    any = __syncthreads_or(any);
    if (threadIdx.x == 0) valid[row] = any ? 1.0f : 0.0f;
}

// ---------------- QKV projection (tf32 MMA) ----------------
// grid: (48 = 3*16 col-tiles, 32 row-tiles). out[b,h,s,e]
__global__ void k_qkv_mma(const float* __restrict__ x,
                          const float* __restrict__ Wq, const float* __restrict__ Wk,
                          const float* __restrict__ Wv,
                          float* __restrict__ pQ, float* __restrict__ pK, float* __restrict__ pV) {
    int nt = blockIdx.x;
    int which = nt >> 4, h = nt & 15;
    int b = blockIdx.y >> 3, s0 = (blockIdx.y & 7) << 7;
    const float* W = (which == 0 ? Wq : which == 1 ? Wk : Wv) + (size_t)h * CD * CDK;
    const float* A = x + ((size_t)b * CS + s0) * CD;
    float* out = (which == 0 ? pQ : which == 1 ? pK : pV)
                 + ((size_t)(b * 16 + h) * CS + s0) * CDK;

    float acc[2][4][4] = {};
    gemm_core<true>(A, CD, W, CDK, CD, acc);

    int lane = threadIdx.x & 31, w = threadIdx.x >> 5, wr = w >> 1, wc = w & 1;
    #pragma unroll
    for (int ms = 0; ms < 2; ms++)
        #pragma unroll
        for (int ns = 0; ns < 4; ns++) {
            int r = wr * 32 + ms * 16 + (lane >> 2);
            int c = wc * 32 + ns * 8 + ((lane & 3) << 1);
            float2 v01 = { acc[ms][ns][0], acc[ms][ns][1] };
            float2 v23 = { acc[ms][ns][2], acc[ms][ns][3] };
            *(float2*)&out[(size_t)r * CDK + c] = v01;
            *(float2*)&out[(size_t)(r + 8) * CDK + c] = v23;
        }
}

// ---------------- energy = (Q K^T)*scale, col-masked (tf32 MMA) ----------------
// grid: (16 k-tiles, 8 q-tiles, 64 bh)
__global__ void k_energy_mma(const float* __restrict__ pQ, const float* __restrict__ pK,
                             const float* __restrict__ valid, float* __restrict__ pE) {
    int bh = blockIdx.z, b = bh >> 4;
    const float* Aq = pQ + ((size_t)bh * CS + (size_t)blockIdx.y * 128) * CDK;
    const float* Bk = pK + ((size_t)bh * CS + (size_t)blockIdx.x * 64) * CDK;
    float* Eo = pE + (size_t)bh * CS * CS + (size_t)blockIdx.y * 128 * CS + (size_t)blockIdx.x * 64;

    float acc[2][4][4] = {};
    gemm_core<false>(Aq, CDK, Bk, CDK, CDK, acc);

    int lane = threadIdx.x & 31, w = threadIdx.x >> 5, wr = w >> 1, wc = w & 1;
    #pragma unroll
    for (int ms = 0; ms < 2; ms++)
        #pragma unroll
        for (int ns = 0; ns < 4; ns++) {
            int r = wr * 32 + ms * 16 + (lane >> 2);
            int c = wc * 32 + ns * 8 + ((lane & 3) << 1);
            int cg = blockIdx.x * 64 + c;
            float cm0 = valid[b * CS + cg];
            float cm1 = valid[b * CS + cg + 1];
            float2 v01, v23;
            v01.x = (cm0 != 0.f) ? acc[ms][ns][0] * 0.125f : -1e30f;
            v01.y = (cm1 != 0.f) ? acc[ms][ns][1] * 0.125f : -1e30f;
            v23.x = (cm0 != 0.f) ? acc[ms][ns][2] * 0.125f : -1e30f;
            v23.y = (cm1 != 0.f) ? acc[ms][ns][3] * 0.125f : -1e30f;
            *(float2*)&Eo[(size_t)r * CS + c] = v01;
            *(float2*)&Eo[(size_t)(r + 8) * CS + c] = v23;
        }
}

// ---------------- row softmax (in place) ----------------
__global__ void k_softmax(float* __restrict__ E) {
    float* row = E + (size_t)blockIdx.x * CS;
    int t = threadIdx.x;
    float4 v = ((float4*)row)[t];
    float m = fmaxf(fmaxf(v.x, v.y), fmaxf(v.z, v.w));
    __shared__ float sm[8];
    __shared__ float ss[8];
    m = warpMax(m);
    if ((t & 31) == 0) sm[t >> 5] = m;
    __syncthreads();
    float mm = sm[0];
    #pragma unroll
    for (int i = 1; i < 8; i++) mm = fmaxf(mm, sm[i]);
    float e0 = __expf(v.x - mm), e1 = __expf(v.y - mm);
    float e2 = __expf(v.z - mm), e3 = __expf(v.w - mm);
    float s = e0 + e1 + e2 + e3;
    s = warpSum(s);
    if ((t & 31) == 0) ss[t >> 5] = s;
    __syncthreads();
    float tot = 0.f;
    #pragma unroll
    for (int i = 0; i < 8; i++) tot += ss[i];
    float inv = 1.0f / tot;
    v.x = e0 * inv; v.y = e1 * inv; v.z = e2 * inv; v.w = e3 * inv;
    ((float4*)row)[t] = v;
}

// ---------------- attn = P @ V, row-masked, into [B,S,D] (tf32 MMA) ----------------
// grid: (8 q-tiles, 64 bh)
__global__ void k_pv_mma(const float* __restrict__ pE, const float* __restrict__ pV,
                         const float* __restrict__ valid, float* __restrict__ pZ) {
    int bh = blockIdx.y, b = bh >> 4, h = bh & 15;
    int q0 = blockIdx.x * 128;
    const float* A = pE + (size_t)bh * CS * CS + (size_t)q0 * CS;
    const float* B = pV + (size_t)bh * CS * CDK;

    float acc[2][4][4] = {};
    gemm_core<true>(A, CS, B, CDK, CS, acc);

    int lane = threadIdx.x & 31, w = threadIdx.x >> 5, wr = w >> 1, wc = w & 1;
    #pragma unroll
    for (int ms = 0; ms < 2; ms++)
        #pragma unroll
        for (int ns = 0; ns < 4; ns++) {
            int r = wr * 32 + ms * 16 + (lane >> 2);
            int c = wc * 32 + ns * 8 + ((lane & 3) << 1);
            float vf0 = valid[b * CS + q0 + r];
            float vf1 = valid[b * CS + q0 + r + 8];
            float2 v01 = { acc[ms][ns][0] * vf0, acc[ms][ns][1] * vf0 };
            float2 v23 = { acc[ms][ns][2] * vf1, acc[ms][ns][3] * vf1 };
            *(float2*)&pZ[(size_t)(b * CS + q0 + r) * CD + h * 64 + c] = v01;
            *(float2*)&pZ[(size_t)(b * CS + q0 + r + 8) * CD + h * 64 + c] = v23;
        }
}

// ---------------- residual add + LayerNorm ----------------
__global__ void k_addln(const float* __restrict__ A, const float* __restrict__ Bv,
                        const float* __restrict__ g, const float* __restrict__ bb,
                        float* __restrict__ out) {
    int row = blockIdx.x, t = threadIdx.x;
    float4 a = ((const float4*)(A  + (size_t)row * CD))[t];
    float4 b = ((const float4*)(Bv + (size_t)row * CD))[t];
    float4 v = {a.x + b.x, a.y + b.y, a.z + b.z, a.w + b.w};
    float s = v.x + v.y + v.z + v.w;
    float q = v.x * v.x + v.y * v.y + v.z * v.z + v.w * v.w;
    __shared__ float sr1[8];
    __shared__ float sr2[8];
    s = warpSum(s); q = warpSum(q);
    if ((t & 31) == 0) { sr1[t >> 5] = s; sr2[t >> 5] = q; }
    __syncthreads();
    float S = 0.f, Q = 0.f;
    #pragma unroll
    for (int i = 0; i < 8; i++) { S += sr1[i]; Q += sr2[i]; }
    float mu = S * (1.0f / CD);
    float var = Q * (1.0f / CD) - mu * mu;
    float rs = rsqrtf(var + LN_EPS);
    float4 gg = ((const float4*)g)[t];
    float4 bv2 = ((const float4*)bb)[t];
    float4 o;
    o.x = (v.x - mu) * rs * gg.x + bv2.x;
    o.y = (v.y - mu) * rs * gg.y + bv2.y;
    o.z = (v.z - mu) * rs * gg.z + bv2.z;
    o.w = (v.w - mu) * rs * gg.w + bv2.w;
    ((float4*)(out + (size_t)row * CD))[t] = o;
}

// ---------------- FC (NT GEMM, tf32 MMA): act(A@W^T + bias) * valid ----------------
// grid: (16 col-tiles, 32 row-tiles)
template <bool RELU>
__global__ void k_fc_mma(const float* __restrict__ A, const float* __restrict__ W,
                         const float* __restrict__ bias, const float* __restrict__ valid,
                         float* __restrict__ out) {
    int j0 = blockIdx.x * 64, r0 = blockIdx.y * 128;
    float acc[2][4][4] = {};
    gemm_core<false>(A + (size_t)r0 * CD, CD, W + (size_t)j0 * CD, CD, CD, acc);

    int lane = threadIdx.x & 31, w = threadIdx.x >> 5, wr = w >> 1, wc = w & 1;
    #pragma unroll
    for (int ms = 0; ms < 2; ms++)
        #pragma unroll
        for (int ns = 0; ns < 4; ns++) {
            int r = wr * 32 + ms * 16 + (lane >> 2);
            int c = wc * 32 + ns * 8 + ((lane & 3) << 1);
            float b0 = bias[j0 + c], b1 = bias[j0 + c + 1];
            float vf0 = valid[r0 + r], vf1 = valid[r0 + r + 8];
            float t0 = acc[ms][ns][0] + b0, t1 = acc[ms][ns][1] + b1;
            float t2 = acc[ms][ns][2] + b0, t3 = acc[ms][ns][3] + b1;
            if (RELU) {
                t0 = fmaxf(t0, 0.f); t1 = fmaxf(t1, 0.f);
                t2 = fmaxf(t2, 0.f); t3 = fmaxf(t3, 0.f);
            }
            float2 v01 = { t0 * vf0, t1 * vf0 };
            float2 v23 = { t2 * vf1, t3 * vf1 };
            *(float2*)&out[(size_t)(r0 + r) * CD + j0 + c] = v01;
            *(float2*)&out[(size_t)(r0 + r + 8) * CD + j0 + c] = v23;
        }
}

// ---------------- launch ----------------
extern "C" void kernel_launch(void* const* d_in, const int* in_sizes, int n_in,
                              void* d_out, int out_size) {
    const float* x     = (const float*)d_in[0];
    const float* Wq    = (const float*)d_in[1];
    const float* Wk    = (const float*)d_in[2];
    const float* Wv    = (const float*)d_in[3];
    const float* ln1_g = (const float*)d_in[4];
    const float* ln1_b = (const float*)d_in[5];
    const float* fc1_w = (const float*)d_in[6];
    const float* fc1_b = (const float*)d_in[7];
    const float* fc2_w = (const float*)d_in[8];
    const float* fc2_b = (const float*)d_in[9];
    const float* ln2_g = (const float*)d_in[10];
    const float* ln2_b = (const float*)d_in[11];
    float* out = (float*)d_out;

    static float *pValid = nullptr, *pQ, *pK, *pV, *pE, *pZ, *pH, *pF, *pG;
    if (!pValid) {
        cudaGetSymbolAddress((void**)&pValid, g_valid);
        cudaGetSymbolAddress((void**)&pQ, g_Q);
        cudaGetSymbolAddress((void**)&pK, g_K);
        cudaGetSymbolAddress((void**)&pV, g_V);
        cudaGetSymbolAddress((void**)&pE, g_E);
        cudaGetSymbolAddress((void**)&pZ, g_Z);
        cudaGetSymbolAddress((void**)&pH, g_Hb);
        cudaGetSymbolAddress((void**)&pF, g_F);
        cudaGetSymbolAddress((void**)&pG, g_G);
    }

    k_valid<<<ROWS, 256>>>(x, pValid);
    k_qkv_mma<<<dim3(48, 32), 256>>>(x, Wq, Wk, Wv, pQ, pK, pV);
    k_energy_mma<<<dim3(16, 8, BH), 256>>>(pQ, pK, pValid, pE);
    k_softmax<<<BH * CS, 256>>>(pE);
    k_pv_mma<<<dim3(8, BH), 256>>>(pE, pV, pValid, pZ);
    k_addln<<<ROWS, 256>>>(x, pZ, ln1_g, ln1_b, pH);
    k_fc_mma<true><<<dim3(16, 32), 256>>>(pH, fc1_w, fc1_b, pValid, pF);
    k_fc_mma<false><<<dim3(16, 32), 256>>>(pF, fc2_w, fc2_b, pValid, pG);
    k_addln<<<ROWS, 256>>>(pH, pG, ln2_g, ln2_b, out);
}

// round 4
// speedup vs baseline: 3.2466x; 1.2196x over previous
#include <cuda_runtime.h>
#include <math.h>
#include <stdint.h>

// Problem dims
constexpr int CB  = 4;
constexpr int CS  = 1024;
constexpr int CD  = 1024;
constexpr int CH  = 16;
constexpr int CDK = 64;
constexpr int BH   = CB * CH;   // 64
constexpr int ROWS = CB * CS;   // 4096
constexpr float LN_EPS = 1e-5f;

// Scratch (device globals: no cudaMalloc allowed)
__device__ float g_valid[ROWS];
__device__ float g_Q[(size_t)BH * CS * CDK];
__device__ float g_K[(size_t)BH * CS * CDK];
__device__ float g_V[(size_t)BH * CS * CDK];
__device__ float g_Z[(size_t)ROWS * CD];
__device__ float g_Hb[(size_t)ROWS * CD];
__device__ float g_F[(size_t)ROWS * CD];
__device__ float g_G[(size_t)ROWS * CD];

// ---------------- helpers ----------------
__device__ __forceinline__ float warpSum(float v) {
    #pragma unroll
    for (int o = 16; o; o >>= 1) v += __shfl_xor_sync(0xffffffffu, v, o);
    return v;
}
__device__ __forceinline__ uint32_t f2tf(float f) {
    uint32_t u;
    asm("cvt.rna.tf32.f32 %0, %1;" : "=r"(u) : "f"(f));
    return u;
}
__device__ __forceinline__ void mma8(float c[4], const uint32_t a[4], const uint32_t b[2]) {
    asm volatile(
        "mma.sync.aligned.m16n8k8.row.col.f32.tf32.tf32.f32 "
        "{%0,%1,%2,%3},{%4,%5,%6,%7},{%8,%9},{%0,%1,%2,%3};"
        : "+f"(c[0]), "+f"(c[1]), "+f"(c[2]), "+f"(c[3])
        : "r"(a[0]), "r"(a[1]), "r"(a[2]), "r"(a[3]), "r"(b[0]), "r"(b[1]));
}

// ---------------- tf32 MMA GEMM core (for QKV/FC) ----------------
// Block tile 128(M) x 64(N), BK=32, 256 threads = 8 warps in 4x2 grid.
template<bool NN>
__device__ __forceinline__ void gemm_core(const float* __restrict__ A, size_t lda,
                                          const float* __restrict__ B, size_t ldb,
                                          int K, float acc[2][4][4]) {
    __shared__ uint32_t sA[128][36];
    __shared__ uint32_t sB[2304];      // NT: [n][36]; NN: [k][72]
    const int t = threadIdx.x, lane = t & 31, w = t >> 5;
    const int wr = w >> 1, wc = w & 1;

    for (int k0 = 0; k0 < K; k0 += 32) {
        #pragma unroll
        for (int i = 0; i < 4; i++) {
            int row = (t >> 3) + (i << 5);
            int c4  = (t & 7) << 2;
            float4 v = *(const float4*)(A + (size_t)row * lda + k0 + c4);
            uint4 u = { f2tf(v.x), f2tf(v.y), f2tf(v.z), f2tf(v.w) };
            *(uint4*)&sA[row][c4] = u;
        }
        if (NN) {
            #pragma unroll
            for (int i = 0; i < 2; i++) {
                int k  = (t >> 4) + (i << 4);
                int n4 = (t & 15) << 2;
                float4 v = *(const float4*)(B + (size_t)(k0 + k) * ldb + n4);
                uint4 u = { f2tf(v.x), f2tf(v.y), f2tf(v.z), f2tf(v.w) };
                *(uint4*)&sB[k * 72 + n4] = u;
            }
        } else {
            #pragma unroll
            for (int i = 0; i < 2; i++) {
                int n  = (t >> 3) + (i << 5);
                int c4 = (t & 7) << 2;
                float4 v = *(const float4*)(B + (size_t)n * ldb + k0 + c4);
                uint4 u = { f2tf(v.x), f2tf(v.y), f2tf(v.z), f2tf(v.w) };
                *(uint4*)&sB[n * 36 + c4] = u;
            }
        }
        __syncthreads();

        #pragma unroll
        for (int ks = 0; ks < 32; ks += 8) {
            uint32_t af[2][4], bf[4][2];
            #pragma unroll
            for (int ms = 0; ms < 2; ms++) {
                int r0 = wr * 32 + ms * 16 + (lane >> 2);
                int kc = ks + (lane & 3);
                af[ms][0] = sA[r0][kc];
                af[ms][1] = sA[r0 + 8][kc];
                af[ms][2] = sA[r0][kc + 4];
                af[ms][3] = sA[r0 + 8][kc + 4];
            }
            #pragma unroll
            for (int ns = 0; ns < 4; ns++) {
                int n0 = wc * 32 + ns * 8 + (lane >> 2);
                int kc = ks + (lane & 3);
                if (NN) {
                    bf[ns][0] = sB[kc * 72 + n0];
                    bf[ns][1] = sB[(kc + 4) * 72 + n0];
                } else {
                    bf[ns][0] = sB[n0 * 36 + kc];
                    bf[ns][1] = sB[n0 * 36 + kc + 4];
                }
            }
            #pragma unroll
            for (int ms = 0; ms < 2; ms++)
                #pragma unroll
                for (int ns = 0; ns < 4; ns++)
                    mma8(acc[ms][ns], af[ms], bf[ns]);
        }
        __syncthreads();
    }
}

// ---------------- valid-row flags ----------------
__global__ void k_valid(const float* __restrict__ x, float* __restrict__ valid) {
    int row = blockIdx.x;
    const float* xr = x + (size_t)row * CD;
    int any = 0;
    for (int i = threadIdx.x; i < CD; i += blockDim.x) any |= (xr[i] != 0.0f);
    any = __syncthreads_or(any);
    if (threadIdx.x == 0) valid[row] = any ? 1.0f : 0.0f;
}

// ---------------- QKV projection (tf32 MMA) ----------------
__global__ void k_qkv_mma(const float* __restrict__ x,
                          const float* __restrict__ Wq, const float* __restrict__ Wk,
                          const float* __restrict__ Wv,
                          float* __restrict__ pQ, float* __restrict__ pK, float* __restrict__ pV) {
    int nt = blockIdx.x;
    int which = nt >> 4, h = nt & 15;
    int b = blockIdx.y >> 3, s0 = (blockIdx.y & 7) << 7;
    const float* W = (which == 0 ? Wq : which == 1 ? Wk : Wv) + (size_t)h * CD * CDK;
    const float* A = x + ((size_t)b * CS + s0) * CD;
    float* out = (which == 0 ? pQ : which == 1 ? pK : pV)
                 + ((size_t)(b * 16 + h) * CS + s0) * CDK;

    float acc[2][4][4] = {};
    gemm_core<true>(A, CD, W, CDK, CD, acc);

    int lane = threadIdx.x & 31, w = threadIdx.x >> 5, wr = w >> 1, wc = w & 1;
    #pragma unroll
    for (int ms = 0; ms < 2; ms++)
        #pragma unroll
        for (int ns = 0; ns < 4; ns++) {
            int r = wr * 32 + ms * 16 + (lane >> 2);
            int c = wc * 32 + ns * 8 + ((lane & 3) << 1);
            float2 v01 = { acc[ms][ns][0], acc[ms][ns][1] };
            float2 v23 = { acc[ms][ns][2], acc[ms][ns][3] };
            *(float2*)&out[(size_t)r * CDK + c] = v01;
            *(float2*)&out[(size_t)(r + 8) * CDK + c] = v23;
        }
}

// ---------------- fused flash attention ----------------
// grid: (8 q-tiles, 64 bh), 256 threads = 8 warps; warp w owns q-rows 16w..16w+15.
__global__ void __launch_bounds__(256)
k_flash(const float* __restrict__ pQ, const float* __restrict__ pK,
        const float* __restrict__ pV, const float* __restrict__ valid,
        float* __restrict__ pZ) {
    __shared__ uint32_t sK[64][68];
    __shared__ uint32_t sV[64][72];
    const int bh = blockIdx.y, b = bh >> 4, h = bh & 15;
    const int q0 = blockIdx.x * 128;
    const int t = threadIdx.x, lane = t & 31, w = t >> 5;
    const int rA = lane >> 2;      // 0..7
    const int qq = lane & 3;       // 0..3
    const float* vbase = valid + b * CS;

    // preload Q fragments (rows 16w + rA, +8)
    const float* Qb = pQ + ((size_t)bh * CS + q0 + w * 16) * CDK;
    uint32_t qf[8][4];
    #pragma unroll
    for (int s = 0; s < 8; s++) {
        int k = s * 8 + qq;
        qf[s][0] = f2tf(Qb[(size_t)rA * CDK + k]);
        qf[s][1] = f2tf(Qb[(size_t)(rA + 8) * CDK + k]);
        qf[s][2] = f2tf(Qb[(size_t)rA * CDK + k + 4]);
        qf[s][3] = f2tf(Qb[(size_t)(rA + 8) * CDK + k + 4]);
    }

    float acc_o[8][4] = {};
    float mA = -INFINITY, mB = -INFINITY, lA = 0.f, lB = 0.f;

    for (int kt = 0; kt < 16; kt++) {
        __syncthreads();
        const float* Kg = pK + ((size_t)bh * CS + kt * 64) * CDK;
        const float* Vg = pV + ((size_t)bh * CS + kt * 64) * CDK;
        #pragma unroll
        for (int i = 0; i < 4; i++) {
            int row = (t >> 4) + i * 16;
            int c4  = (t & 15) << 2;
            float4 kv = *(const float4*)(Kg + (size_t)row * CDK + c4);
            float4 vv = *(const float4*)(Vg + (size_t)row * CDK + c4);
            uint4 ku = { f2tf(kv.x), f2tf(kv.y), f2tf(kv.z), f2tf(kv.w) };
            uint4 vu = { f2tf(vv.x), f2tf(vv.y), f2tf(vv.z), f2tf(vv.w) };
            *(uint4*)&sK[row][c4] = ku;
            *(uint4*)&sV[row][c4] = vu;
        }
        __syncthreads();

        // S = Q K^T (128x64)
        float accs[8][4] = {};
        #pragma unroll
        for (int s = 0; s < 8; s++) {
            int kc = s * 8 + qq;
            #pragma unroll
            for (int j = 0; j < 8; j++) {
                int n0 = j * 8 + rA;
                uint32_t bf[2] = { sK[n0][kc], sK[n0][kc + 4] };
                mma8(accs[j], qf[s], bf);
            }
        }

        // mask + scale, row max
        float rmaxA = -INFINITY, rmaxB = -INFINITY;
        #pragma unroll
        for (int j = 0; j < 8; j++) {
            int cg = kt * 64 + j * 8 + (qq << 1);
            float cm0 = vbase[cg], cm1 = vbase[cg + 1];
            accs[j][0] = (cm0 != 0.f) ? accs[j][0] * 0.125f : -1e30f;
            accs[j][1] = (cm1 != 0.f) ? accs[j][1] * 0.125f : -1e30f;
            accs[j][2] = (cm0 != 0.f) ? accs[j][2] * 0.125f : -1e30f;
            accs[j][3] = (cm1 != 0.f) ? accs[j][3] * 0.125f : -1e30f;
            rmaxA = fmaxf(rmaxA, fmaxf(accs[j][0], accs[j][1]));
            rmaxB = fmaxf(rmaxB, fmaxf(accs[j][2], accs[j][3]));
        }
        rmaxA = fmaxf(rmaxA, __shfl_xor_sync(~0u, rmaxA, 1));
        rmaxA = fmaxf(rmaxA, __shfl_xor_sync(~0u, rmaxA, 2));
        rmaxB = fmaxf(rmaxB, __shfl_xor_sync(~0u, rmaxB, 1));
        rmaxB = fmaxf(rmaxB, __shfl_xor_sync(~0u, rmaxB, 2));

        float mnA = fmaxf(mA, rmaxA), mnB = fmaxf(mB, rmaxB);
        float aAf = __expf(mA - mnA), aBf = __expf(mB - mnB);
        mA = mnA; mB = mnB;

        float sumA = 0.f, sumB = 0.f;
        uint32_t pt[8][4];
        #pragma unroll
        for (int j = 0; j < 8; j++) {
            float p0 = __expf(accs[j][0] - mA), p1 = __expf(accs[j][1] - mA);
            float p2 = __expf(accs[j][2] - mB), p3 = __expf(accs[j][3] - mB);
            sumA += p0 + p1; sumB += p2 + p3;
            pt[j][0] = f2tf(p0); pt[j][1] = f2tf(p1);
            pt[j][2] = f2tf(p2); pt[j][3] = f2tf(p3);
            acc_o[j][0] *= aAf; acc_o[j][1] *= aAf;
            acc_o[j][2] *= aBf; acc_o[j][3] *= aBf;
        }
        sumA += __shfl_xor_sync(~0u, sumA, 1); sumA += __shfl_xor_sync(~0u, sumA, 2);
        sumB += __shfl_xor_sync(~0u, sumB, 1); sumB += __shfl_xor_sync(~0u, sumB, 2);
        lA = lA * aAf + sumA; lB = lB * aBf + sumB;

        // O += P V : build A-frags from pt via quad shuffles (accum->A permutation)
        #pragma unroll
        for (int s = 0; s < 8; s++) {
            int src0 = (lane & ~3) | (qq >> 1);
            int src1 = src0 + 2;
            uint32_t v00 = __shfl_sync(~0u, pt[s][0], src0);
            uint32_t v01 = __shfl_sync(~0u, pt[s][1], src0);
            uint32_t v10 = __shfl_sync(~0u, pt[s][2], src0);
            uint32_t v11 = __shfl_sync(~0u, pt[s][3], src0);
            uint32_t w00 = __shfl_sync(~0u, pt[s][0], src1);
            uint32_t w01 = __shfl_sync(~0u, pt[s][1], src1);
            uint32_t w10 = __shfl_sync(~0u, pt[s][2], src1);
            uint32_t w11 = __shfl_sync(~0u, pt[s][3], src1);
            uint32_t af[4];
            af[0] = (qq & 1) ? v01 : v00;   // P[r   ][8s+qq]
            af[1] = (qq & 1) ? v11 : v10;   // P[r+8 ][8s+qq]
            af[2] = (qq & 1) ? w01 : w00;   // P[r   ][8s+qq+4]
            af[3] = (qq & 1) ? w11 : w10;   // P[r+8 ][8s+qq+4]
            int kc = s * 8 + qq;
            #pragma unroll
            for (int j = 0; j < 8; j++) {
                int n0 = j * 8 + rA;
                uint32_t bf[2] = { sV[kc][n0], sV[kc + 4][n0] };
                mma8(acc_o[j], af, bf);
            }
        }
    }

    // epilogue: normalize, q-row mask, write Z[b,s,d]
    float invA = 1.f / lA, invB = 1.f / lB;
    int qrA = q0 + w * 16 + rA, qrB = qrA + 8;
    float vfA = vbase[qrA] * invA, vfB = vbase[qrB] * invB;
    #pragma unroll
    for (int j = 0; j < 8; j++) {
        int c = j * 8 + (qq << 1);
        float2 v01 = { acc_o[j][0] * vfA, acc_o[j][1] * vfA };
        float2 v23 = { acc_o[j][2] * vfB, acc_o[j][3] * vfB };
        *(float2*)&pZ[(size_t)(b * CS + qrA) * CD + h * 64 + c] = v01;
        *(float2*)&pZ[(size_t)(b * CS + qrB) * CD + h * 64 + c] = v23;
    }
}

// ---------------- residual add + LayerNorm ----------------
__global__ void k_addln(const float* __restrict__ A, const float* __restrict__ Bv,
                        const float* __restrict__ g, const float* __restrict__ bb,
                        float* __restrict__ out) {
    int row = blockIdx.x, t = threadIdx.x;
    float4 a = ((const float4*)(A  + (size_t)row * CD))[t];
    float4 b = ((const float4*)(Bv + (size_t)row * CD))[t];
    float4 v = {a.x + b.x, a.y + b.y, a.z + b.z, a.w + b.w};
    float s = v.x + v.y + v.z + v.w;
    float q = v.x * v.x + v.y * v.y + v.z * v.z + v.w * v.w;
    __shared__ float sr1[8];
    __shared__ float sr2[8];
    s = warpSum(s); q = warpSum(q);
    if ((t & 31) == 0) { sr1[t >> 5] = s; sr2[t >> 5] = q; }
    __syncthreads();
    float S = 0.f, Q = 0.f;
    #pragma unroll
    for (int i = 0; i < 8; i++) { S += sr1[i]; Q += sr2[i]; }
    float mu = S * (1.0f / CD);
    float var = Q * (1.0f / CD) - mu * mu;
    float rs = rsqrtf(var + LN_EPS);
    float4 gg = ((const float4*)g)[t];
    float4 bv2 = ((const float4*)bb)[t];
    float4 o;
    o.x = (v.x - mu) * rs * gg.x + bv2.x;
    o.y = (v.y - mu) * rs * gg.y + bv2.y;
    o.z = (v.z - mu) * rs * gg.z + bv2.z;
    o.w = (v.w - mu) * rs * gg.w + bv2.w;
    ((float4*)(out + (size_t)row * CD))[t] = o;
}

// ---------------- FC (NT GEMM, tf32 MMA) ----------------
template <bool RELU>
__global__ void k_fc_mma(const float* __restrict__ A, const float* __restrict__ W,
                         const float* __restrict__ bias, const float* __restrict__ valid,
                         float* __restrict__ out) {
    int j0 = blockIdx.x * 64, r0 = blockIdx.y * 128;
    float acc[2][4][4] = {};
    gemm_core<false>(A + (size_t)r0 * CD, CD, W + (size_t)j0 * CD, CD, CD, acc);

    int lane = threadIdx.x & 31, w = threadIdx.x >> 5, wr = w >> 1, wc = w & 1;
    #pragma unroll
    for (int ms = 0; ms < 2; ms++)
        #pragma unroll
        for (int ns = 0; ns < 4; ns++) {
            int r = wr * 32 + ms * 16 + (lane >> 2);
            int c = wc * 32 + ns * 8 + ((lane & 3) << 1);
            float b0 = bias[j0 + c], b1 = bias[j0 + c + 1];
            float vf0 = valid[r0 + r], vf1 = valid[r0 + r + 8];
            float t0 = acc[ms][ns][0] + b0, t1 = acc[ms][ns][1] + b1;
            float t2 = acc[ms][ns][2] + b0, t3 = acc[ms][ns][3] + b1;
            if (RELU) {
                t0 = fmaxf(t0, 0.f); t1 = fmaxf(t1, 0.f);
                t2 = fmaxf(t2, 0.f); t3 = fmaxf(t3, 0.f);
            }
            float2 v01 = { t0 * vf0, t1 * vf0 };
            float2 v23 = { t2 * vf1, t3 * vf1 };
            *(float2*)&out[(size_t)(r0 + r) * CD + j0 + c] = v01;
            *(float2*)&out[(size_t)(r0 + r + 8) * CD + j0 + c] = v23;
        }
}

// ---------------- launch ----------------
extern "C" void kernel_launch(void* const* d_in, const int* in_sizes, int n_in,
                              void* d_out, int out_size) {
    const float* x     = (const float*)d_in[0];
    const float* Wq    = (const float*)d_in[1];
    const float* Wk    = (const float*)d_in[2];
    const float* Wv    = (const float*)d_in[3];
    const float* ln1_g = (const float*)d_in[4];
    const float* ln1_b = (const float*)d_in[5];
    const float* fc1_w = (const float*)d_in[6];
    const float* fc1_b = (const float*)d_in[7];
    const float* fc2_w = (const float*)d_in[8];
    const float* fc2_b = (const float*)d_in[9];
    const float* ln2_g = (const float*)d_in[10];
    const float* ln2_b = (const float*)d_in[11];
    float* out = (float*)d_out;

    static float *pValid = nullptr, *pQ, *pK, *pV, *pZ, *pH, *pF, *pG;
    if (!pValid) {
        cudaGetSymbolAddress((void**)&pValid, g_valid);
        cudaGetSymbolAddress((void**)&pQ, g_Q);
        cudaGetSymbolAddress((void**)&pK, g_K);
        cudaGetSymbolAddress((void**)&pV, g_V);
        cudaGetSymbolAddress((void**)&pZ, g_Z);
        cudaGetSymbolAddress((void**)&pH, g_Hb);
        cudaGetSymbolAddress((void**)&pF, g_F);
        cudaGetSymbolAddress((void**)&pG, g_G);
    }

    k_valid<<<ROWS, 256>>>(x, pValid);
    k_qkv_mma<<<dim3(48, 32), 256>>>(x, Wq, Wk, Wv, pQ, pK, pV);
    k_flash<<<dim3(8, BH), 256>>>(pQ, pK, pV, pValid, pZ);
    k_addln<<<ROWS, 256>>>(x, pZ, ln1_g, ln1_b, pH);
    k_fc_mma<true><<<dim3(16, 32), 256>>>(pH, fc1_w, fc1_b, pValid, pF);
    k_fc_mma<false><<<dim3(16, 32), 256>>>(pF, fc2_w, fc2_b, pValid, pG);
    k_addln<<<ROWS, 256>>>(pH, pG, ln2_g, ln2_b, out);
}